// round 15
// baseline (speedup 1.0000x reference)
#include <cuda_runtime.h>
#include <cstdint>
#include <cstddef>

#define NN 2048
#define BB 8
#define TT 12
#define DD 64
#define MX 6144
#define MH 512
static constexpr size_t MXN = (size_t)MX*NN;
static constexpr size_t MHN = (size_t)MH*NN;
static constexpr size_t NN2 = (size_t)NN*NN;

// ---- exact fp32 scratch ----
static constexpr size_t O_ST=0, O_HF=O_ST+12*MHN, O_RF=O_HF+MHN, NFB=O_RF+MHN;
// ---- tf32-rounded scratch (T_S2 MUST follow T_A: stacked [A';S2']) ----
// x / xd buffers are T-MAJOR: row = t*512 + b*64 + d
static constexpr size_t T_A=0, T_S2=T_A+NN2, T_AT=T_S2+NN2, T_X=T_AT+NN2,
 T_XD1=T_X+MXN, T_XD2=T_XD1+MXN,
 T_H=T_XD2+MXN, T_HD1=T_H+MHN, T_HD2=T_HD1+MHN,
 T_G=T_HD2+MHN, T_GD1=T_G+MHN, T_GD2=T_GD1+MHN,
 T_WG=T_GD2+MHN, T_WC=T_WG+384*128, NTB=T_WC+384*64;

__device__ float g_fbuf[NFB];
__device__ float g_tbuf[NTB];

// ---------------- helpers ----------------
__device__ __forceinline__ uint32_t smem_u32(const void* p){
    uint32_t a;
    asm("{ .reg .u64 t; cvta.to.shared.u64 t, %1; cvt.u32.u64 %0, t; }" : "=r"(a) : "l"(p));
    return a;
}
#define SWZ(x) ((x) ^ (((x) >> 3) & 0x70))

__device__ __forceinline__ float tf32r(float v){
    uint32_t r; asm("cvt.rna.tf32.f32 %0, %1;" : "=r"(r) : "f"(v));
    return __uint_as_float(r);
}
__device__ __forceinline__ uint32_t lds_u(uint32_t a){
    uint32_t v; asm volatile("ld.shared.b32 %0, [%1];" : "=r"(v) : "r"(a)); return v;
}
__device__ __forceinline__ void cpa16(uint32_t d, const void* s){
    asm volatile("cp.async.cg.shared.global [%0], [%1], 16;" :: "r"(d), "l"(s) : "memory");
}
__device__ __forceinline__ void mma1688(float* c, const uint32_t* a, uint32_t b0, uint32_t b1){
    asm volatile("mma.sync.aligned.m16n8k8.row.col.f32.tf32.tf32.f32 "
        "{%0,%1,%2,%3}, {%4,%5,%6,%7}, {%8,%9}, {%0,%1,%2,%3};"
        : "+f"(c[0]), "+f"(c[1]), "+f"(c[2]), "+f"(c[3])
        : "r"(a[0]), "r"(a[1]), "r"(a[2]), "r"(a[3]), "r"(b0), "r"(b1));
}

// ---------------- diffusion tile core (tf32): out[m][n] = sum_k act[m][k] * B[n][k] ----------------
// R13 config: 8 warps (256 threads), warp tile 32x64. K=2048 in 64 chunks of 32 floats.
// 6 smem stages, chunk PAIRS, 1 sync per 2 chunks.
// S2M=1: out1 = tf32(2*v - I). S2M=0: n<NN -> out1, else out2 (at n-NN). Outputs tf32.
template<int S2M>
__device__ __forceinline__ void diffuse_tile(
    const float* __restrict__ actT, const float* __restrict__ bTp,
    float* __restrict__ out1, float* __restrict__ out2,
    int m0, int n0, uint32_t sb)
{
    constexpr int ABYTES = 128 * 128;
    constexpr int STG = ABYTES + 16384;         // 32KB/stage
    int tid = threadIdx.x, lane = tid & 31, wid = tid >> 5;
    int wm = wid >> 1, wn = wid & 1;

    const char* aT = (const char*)(actT + (size_t)m0 * NN);
    const char* bT = (const char*)(bTp  + (size_t)n0 * NN);

    auto load_chunk = [&](int kc, int stg){
        const char* As = aT + (size_t)kc * 128;
        const char* Bs = bT + (size_t)kc * 128;
        uint32_t s = sb + stg * STG;
        #pragma unroll
        for (int i = 0; i < 4; i++){
            int q = tid + (i << 8);
            int row = q >> 3, c = (q & 7) << 4;
            cpa16(s + SWZ((uint32_t)(row*128 + c)), As + (size_t)row*8192 + c);
        }
        #pragma unroll
        for (int i = 0; i < 4; i++){
            int q = tid + (i << 8);
            int row = q >> 3, c = (q & 7) << 4;
            cpa16(s + ABYTES + SWZ((uint32_t)(row*128 + c)), Bs + (size_t)row*8192 + c);
        }
    };

    float acc[2][8][4];
    #pragma unroll
    for (int i = 0; i < 2; i++)
        #pragma unroll
        for (int j = 0; j < 8; j++)
            #pragma unroll
            for (int q = 0; q < 4; q++) acc[i][j][q] = 0.f;

    load_chunk(0, 0); load_chunk(1, 1);
    asm volatile("cp.async.commit_group;" ::: "memory");
    load_chunk(2, 2); load_chunk(3, 3);
    asm volatile("cp.async.commit_group;" ::: "memory");

    uint32_t af[2][2][4], bfr[2][8][2];
    auto load_frags = [&](uint32_t stgBase, int s, int buf){
        uint32_t sA = stgBase, sB = stgBase + ABYTES;
        uint32_t c0 = (uint32_t)(s*32 + ((lane & 3) << 2));
        #pragma unroll
        for (int i = 0; i < 2; i++){
            int row = wm*32 + i*16 + (lane >> 2);
            af[buf][i][0] = lds_u(sA + SWZ((uint32_t)(row*128)     + c0));
            af[buf][i][1] = lds_u(sA + SWZ((uint32_t)((row+8)*128) + c0));
            af[buf][i][2] = lds_u(sA + SWZ((uint32_t)(row*128)     + c0 + 16));
            af[buf][i][3] = lds_u(sA + SWZ((uint32_t)((row+8)*128) + c0 + 16));
        }
        #pragma unroll
        for (int j = 0; j < 8; j++){
            int n = wn*64 + j*8 + (lane >> 2);
            bfr[buf][j][0] = lds_u(sB + SWZ((uint32_t)(n*128) + c0));
            bfr[buf][j][1] = lds_u(sB + SWZ((uint32_t)(n*128) + c0 + 16));
        }
    };

    for (int kc = 0; kc < 64; kc += 2){
        asm volatile("cp.async.wait_group 1;" ::: "memory");
        __syncthreads();
        uint32_t st0 = sb + (kc % 6) * STG;
        uint32_t st1 = sb + ((kc + 1) % 6) * STG;

        load_frags(st0, 0, 0);
        #pragma unroll
        for (int s = 0; s < 8; s++){
            if (s < 7){
                int sn = s + 1;
                load_frags((sn < 4) ? st0 : st1, sn & 3, sn & 1);
            }
            int b = s & 1;
            #pragma unroll
            for (int j = 0; j < 8; j++){
                mma1688(acc[0][j], af[b][0], bfr[b][j][0], bfr[b][j][1]);
                mma1688(acc[1][j], af[b][1], bfr[b][j][0], bfr[b][j][1]);
            }
        }
        if (kc + 4 < 64){
            load_chunk(kc + 4, (kc + 4) % 6);
            load_chunk(kc + 5, (kc + 5) % 6);
        }
        asm volatile("cp.async.commit_group;" ::: "memory");
    }

    float* o; int cb;
    if (S2M || n0 < NN){ o = out1; cb = n0; }
    else { o = out2; cb = n0 - NN; }
    #pragma unroll
    for (int i = 0; i < 2; i++){
        int rowb = m0 + wm*32 + i*16 + (lane >> 2);
        #pragma unroll
        for (int j = 0; j < 8; j++){
            int col = cb + wn*64 + j*8 + (lane & 3)*2;
            #pragma unroll
            for (int h = 0; h < 2; h++){
                int row = rowb + h*8;
                size_t off = (size_t)row * NN + col;
                float2 v; v.x = acc[i][j][h*2]; v.y = acc[i][j][h*2+1];
                if (S2M){
                    v.x = 2.f*v.x - ((row == col)   ? 1.f : 0.f);
                    v.y = 2.f*v.y - ((row == col+1) ? 1.f : 0.f);
                }
                v.x = tf32r(v.x); v.y = tf32r(v.y);
                *(float2*)&o[off] = v;
            }
        }
    }
}

// standalone diffuse kernel (256 threads)
template<int S2M>
__global__ __launch_bounds__(256)
void diffuse_kernel(const float* __restrict__ actT, const float* __restrict__ bTp,
                    float* __restrict__ out1, float* __restrict__ out2)
{
    extern __shared__ char smem[];
    diffuse_tile<S2M>(actT, bTp, out1, out2, blockIdx.y << 7, blockIdx.x << 7, smem_u32(smem));
}

// ---------------- gate/cand MMA cores (256 threads) ----------------
#define FS_PAD 136
#define FS_B (32*FS_PAD*4)

template<int MO>   // 128 = gate, 64 = cand
__device__ __forceinline__ void gc_mma_core(
    const float* const* srcs, const float* Wt, int n0,
    float acc[2][8][4], int lane, int wm, int wn, uint32_t sb)
{
    constexpr int WSB = MO * 144;
    constexpr int STG = WSB + FS_B;
    constexpr int NJ = (MO == 128) ? 8 : 4;
    int tid = threadIdx.x;

    auto load_chunk = [&](int kc, int stg){
        uint32_t s = sb + stg * STG;
        const float* wsrc = Wt + kc*32;
        #pragma unroll
        for (int i = 0; i < MO*8/256; i++){
            int q = tid + (i << 8);
            int row = q >> 3, c16 = (q & 7) << 4;
            cpa16(s + (uint32_t)(row*144 + c16), (const char*)(wsrc + (size_t)row*384) + c16);
        }
        const float* fsrc = srcs[kc >> 1] + (size_t)((kc & 1) << 5)*NN + n0;
        #pragma unroll
        for (int i = 0; i < 4; i++){
            int q = tid + (i << 8);
            int row = q >> 5, c16 = (q & 31) << 4;
            cpa16(s + WSB + (uint32_t)(row*(FS_PAD*4) + c16), (const char*)(fsrc + (size_t)row*NN) + c16);
        }
    };

    load_chunk(0, 0); asm volatile("cp.async.commit_group;" ::: "memory");
    load_chunk(1, 1); asm volatile("cp.async.commit_group;" ::: "memory");

    for (int kc = 0; kc < 12; kc++){
        asm volatile("cp.async.wait_group 1;" ::: "memory");
        __syncthreads();
        uint32_t sW = sb + (kc % 3) * STG, sF = sW + WSB;
        #pragma unroll
        for (int s = 0; s < 4; s++){
            int k = s*8 + (lane & 3);
            uint32_t a[2][4];
            #pragma unroll
            for (int i = 0; i < 2; i++){
                int row = wm*32 + i*16 + (lane >> 2);
                a[i][0] = lds_u(sW + (uint32_t)(row*144     + k*4));
                a[i][1] = lds_u(sW + (uint32_t)((row+8)*144 + k*4));
                a[i][2] = lds_u(sW + (uint32_t)(row*144     + (k+4)*4));
                a[i][3] = lds_u(sW + (uint32_t)((row+8)*144 + (k+4)*4));
            }
            #pragma unroll
            for (int j = 0; j < NJ; j++){
                int n = wn*(NJ*8) + j*8 + (lane >> 2);
                uint32_t b0 = lds_u(sF + (uint32_t)(k*(FS_PAD*4)     + n*4));
                uint32_t b1 = lds_u(sF + (uint32_t)((k+4)*(FS_PAD*4) + n*4));
                mma1688(acc[0][j], a[0], b0, b1);
                mma1688(acc[1][j], a[1], b0, b1);
            }
        }
        if (kc + 2 < 12) load_chunk(kc + 2, (kc + 2) % 3);
        asm volatile("cp.async.commit_group;" ::: "memory");
    }
}

__global__ __launch_bounds__(256)
void gate_mma_kernel(const float* __restrict__ bg, int t){
    extern __shared__ char smem[];
    uint32_t sb = smem_u32(smem);
    int tid = threadIdx.x, lane = tid & 31, wid = tid >> 5;
    int wm = wid >> 1, wn = wid & 1;
    int n0 = blockIdx.x << 7, b = blockIdx.y;
    // x/xd buffers t-major: row base = t*512 + b*64
    const float* srcs[6] = {
        g_tbuf + T_X   + ((size_t)t*MH + b*DD)*NN,
        g_tbuf + T_H   + (size_t)b*DD*NN,
        g_tbuf + T_XD1 + ((size_t)t*MH + b*DD)*NN,
        g_tbuf + T_HD1 + (size_t)b*DD*NN,
        g_tbuf + T_XD2 + ((size_t)t*MH + b*DD)*NN,
        g_tbuf + T_HD2 + (size_t)b*DD*NN };
    float acc[2][8][4];
    #pragma unroll
    for (int i=0;i<2;i++) for (int j=0;j<8;j++) for (int q=0;q<4;q++) acc[i][j][q]=0.f;
    gc_mma_core<128>(srcs, g_tbuf + T_WG, n0, acc, lane, wm, wn, sb);

    #pragma unroll
    for (int i = 0; i < 2; i++){
        int ob = wm*32 + i*16 + (lane >> 2);
        #pragma unroll
        for (int j = 0; j < 8; j++){
            int n = n0 + wn*64 + j*8 + (lane & 3)*2;
            #pragma unroll
            for (int h = 0; h < 2; h++){
                int o = ob + h*8;
                float2 v; v.x = acc[i][j][h*2] + bg[o]; v.y = acc[i][j][h*2+1] + bg[o];
                v.x = 1.f/(1.f + __expf(-v.x)); v.y = 1.f/(1.f + __expf(-v.y));
                if (o < 64){
                    size_t idx = ((size_t)b*DD + o)*NN + n;
                    float2 hh = *(const float2*)&g_fbuf[O_HF + idx];
                    float2 g; g.x = tf32r(v.x*hh.x); g.y = tf32r(v.y*hh.y);
                    *(float2*)&g_tbuf[T_G + idx] = g;
                } else {
                    *(float2*)&g_fbuf[O_RF + ((size_t)b*DD + (o-64))*NN + n] = v;
                }
            }
        }
    }
}

__global__ __launch_bounds__(256)
void cand_mma_kernel(const float* __restrict__ bc, int t){
    extern __shared__ char smem[];
    uint32_t sb = smem_u32(smem);
    int tid = threadIdx.x, lane = tid & 31, wid = tid >> 5;
    int wm = wid >> 2, wn = wid & 3;
    int n0 = blockIdx.x << 7, b = blockIdx.y;
    const float* srcs[6] = {
        g_tbuf + T_X   + ((size_t)t*MH + b*DD)*NN,
        g_tbuf + T_G   + (size_t)b*DD*NN,
        g_tbuf + T_XD1 + ((size_t)t*MH + b*DD)*NN,
        g_tbuf + T_GD1 + (size_t)b*DD*NN,
        g_tbuf + T_XD2 + ((size_t)t*MH + b*DD)*NN,
        g_tbuf + T_GD2 + (size_t)b*DD*NN };
    float acc[2][8][4];
    #pragma unroll
    for (int i=0;i<2;i++) for (int j=0;j<8;j++) for (int q=0;q<4;q++) acc[i][j][q]=0.f;
    gc_mma_core<64>(srcs, g_tbuf + T_WC, n0, acc, lane, wm, wn, sb);

    #pragma unroll
    for (int i = 0; i < 2; i++){
        int ob = wm*32 + i*16 + (lane >> 2);
        #pragma unroll
        for (int j = 0; j < 4; j++){
            int n = n0 + wn*32 + j*8 + (lane & 3)*2;
            #pragma unroll
            for (int h = 0; h < 2; h++){
                int o = ob + h*8;
                size_t idx = ((size_t)b*DD + o)*NN + n;
                float2 hc; hc.x = tanhf(acc[i][j][h*2] + bc[o]); hc.y = tanhf(acc[i][j][h*2+1] + bc[o]);
                float2 r  = *(const float2*)&g_fbuf[O_RF + idx];
                float2 hh = *(const float2*)&g_fbuf[O_HF + idx];
                float2 hn; hn.x = r.x*hh.x + (1.f-r.x)*hc.x; hn.y = r.y*hh.y + (1.f-r.y)*hc.y;
                *(float2*)&g_fbuf[O_HF + idx] = hn;
                float2 ht; ht.x = tf32r(hn.x); ht.y = tf32r(hn.y);
                *(float2*)&g_tbuf[T_H + idx] = ht;
                *(float2*)&g_fbuf[O_ST + (size_t)t*MHN + idx] = hn;
            }
        }
    }
}

// ---------------- prep kernels ----------------
__global__ __launch_bounds__(256) void prep_adj_kernel(const float* __restrict__ adj){
    size_t i = ((size_t)blockIdx.x * 256 + threadIdx.x) * 4;
    float4 v = *(const float4*)&adj[i];
    float4 t; t.x = tf32r(v.x); t.y = tf32r(v.y); t.z = tf32r(v.z); t.w = tf32r(v.w);
    *(float4*)&g_tbuf[T_A + i] = t;
}

__global__ __launch_bounds__(256) void prep_adjT_kernel(const float* __restrict__ adj){
    __shared__ float S[32][33];
    int x0 = blockIdx.x << 5, y0 = blockIdx.y << 5;
    int tx = threadIdx.x & 31, ty = threadIdx.x >> 5;
    #pragma unroll
    for (int i = 0; i < 4; i++)
        S[ty + i*8][tx] = adj[(size_t)(y0 + ty + i*8)*NN + x0 + tx];
    __syncthreads();
    #pragma unroll
    for (int i = 0; i < 4; i++)
        g_tbuf[T_AT + (size_t)(x0 + ty + i*8)*NN + y0 + tx] = tf32r(S[tx][ty + i*8]);
}

__global__ void prep_W_kernel(const float* __restrict__ W, float* __restrict__ Wt, int O){
    int i = blockIdx.x * 256 + threadIdx.x;
    if (i >= 384*O) return;
    int k = i / O, o = i % O;
    Wt[(size_t)o*384 + k] = tf32r(W[i]);
}

// transpose [rr][n][d] -> feature-major rows. XMAJ=1: rr=b*TT+t -> dest row (t*BB+b)*64+d.
template<int WF, int XMAJ>
__global__ __launch_bounds__(256)
void prep_T_kernel(const float* __restrict__ src, float* __restrict__ dstT,
                   float* __restrict__ dstF){
    __shared__ float S[64][65];
    int n0 = blockIdx.x << 6, rr = blockIdx.y;
    int rdest = XMAJ ? ((rr % TT) * BB + rr / TT) : rr;
    const float* sp = src + ((size_t)rr * NN + n0) * DD;
    #pragma unroll
    for (int i = 0; i < 16; i++){
        int q = threadIdx.x + (i << 8);
        S[q >> 6][q & 63] = sp[(size_t)(q >> 6) * DD + (q & 63)];
    }
    __syncthreads();
    #pragma unroll
    for (int i = 0; i < 16; i++){
        int q = threadIdx.x + (i << 8);
        int d = q >> 6, nl = q & 63;
        float v = S[nl][d];
        size_t off = ((size_t)rdest * DD + d) * NN + n0 + nl;
        dstT[off] = tf32r(v);
        if (WF) dstF[off] = v;
    }
}

// ---------------- output assembly ----------------
// per-timestep residual output: out[b][t][n][d] = x + state(t); grid (NN/64, BB)
__global__ __launch_bounds__(256)
void final_out_kernel(const float* __restrict__ x, float* __restrict__ out, int t){
    __shared__ float S[64][65];
    int n0 = blockIdx.x << 6, b = blockIdx.y;
    const float* st = g_fbuf + O_ST + (size_t)t*MHN + (size_t)b*DD*NN;
    #pragma unroll
    for (int i = 0; i < 16; i++){
        int q = threadIdx.x + (i << 8);
        int d = q >> 6, nl = q & 63;
        S[d][nl] = st[(size_t)d*NN + n0 + nl];
    }
    __syncthreads();
    #pragma unroll
    for (int i = 0; i < 16; i++){
        int q = threadIdx.x + (i << 8);
        int nl = q >> 6, d = q & 63;
        size_t off = (((size_t)b*TT + t)*NN + n0 + nl)*DD + d;
        out[off] = x[off] + S[d][nl];
    }
}

__global__ __launch_bounds__(256)
void last_out_kernel(float* __restrict__ outL){
    __shared__ float S[64][65];
    int n0 = blockIdx.x << 6, b = blockIdx.y;
    const float* hp = g_fbuf + O_HF + (size_t)b*DD*NN;
    #pragma unroll
    for (int i = 0; i < 16; i++){
        int q = threadIdx.x + (i << 8);
        int d = q >> 6, nl = q & 63;
        S[d][nl] = hp[(size_t)d*NN + n0 + nl];
    }
    __syncthreads();
    #pragma unroll
    for (int i = 0; i < 16; i++){
        int q = threadIdx.x + (i << 8);
        int nl = q >> 6, d = q & 63;
        outL[((size_t)b*NN + n0 + nl)*DD + d] = S[d][nl];
    }
}

// ---------------- launch ----------------
extern "C" void kernel_launch(void* const* d_in, const int* in_sizes, int n_in,
                              void* d_out, int out_size) {
    const float* x   = (const float*)d_in[0];
    const float* h0  = (const float*)d_in[1];
    const float* adj = (const float*)d_in[2];
    const float* Wg  = (const float*)d_in[3];
    const float* bg  = (const float*)d_in[4];
    const float* Wc  = (const float*)d_in[5];
    const float* bc  = (const float*)d_in[6];
    float* out = (float*)d_out;

    void *pf, *pt;
    cudaGetSymbolAddress(&pf, g_fbuf);
    cudaGetSymbolAddress(&pt, g_tbuf);
    float* F = (float*)pf;
    float* T = (float*)pt;

    const int DSM = 6 * 32768;                    // 196608 bytes
    const int GSM = 3 * (128*144 + FS_B);
    const int CSM = 3 * (64*144  + FS_B);
    cudaFuncSetAttribute(diffuse_kernel<0>, cudaFuncAttributeMaxDynamicSharedMemorySize, DSM);
    cudaFuncSetAttribute(diffuse_kernel<1>, cudaFuncAttributeMaxDynamicSharedMemorySize, DSM);
    cudaFuncSetAttribute(gate_mma_kernel,   cudaFuncAttributeMaxDynamicSharedMemorySize, GSM);
    cudaFuncSetAttribute(cand_mma_kernel,   cudaFuncAttributeMaxDynamicSharedMemorySize, CSM);

    // fork stream + events (host objects; created fresh each call, leaked — 2 calls total)
    cudaStream_t s2;
    cudaStreamCreateWithFlags(&s2, cudaStreamNonBlocking);
    cudaEvent_t evS2, evS2done, evX[TT], evC[TT];
    cudaEventCreateWithFlags(&evS2,     cudaEventDisableTiming);
    cudaEventCreateWithFlags(&evS2done, cudaEventDisableTiming);
    for (int t = 0; t < TT; t++){
        cudaEventCreateWithFlags(&evX[t], cudaEventDisableTiming);
        cudaEventCreateWithFlags(&evC[t], cudaEventDisableTiming);
    }

    // ---- s2: x transpose (depends only on input x), overlaps adj prep + S2 ----
    prep_T_kernel<0,1><<<dim3(NN/64, BB*TT), 256, 0, s2>>>(x, T+T_X, nullptr);

    // ---- main: adj prep + S2' = tf32(2*A@A - I) ----
    prep_adj_kernel<<<(int)(NN2/1024), 256>>>(adj);
    prep_adjT_kernel<<<dim3(NN/32, NN/32), 256>>>(adj);
    diffuse_kernel<1><<<dim3(16,16),256,DSM>>>(T+T_A, T+T_AT, T+T_S2, nullptr);
    cudaEventRecord(evS2, 0);

    // ---- main: recurrence-only prep ----
    prep_W_kernel<<<(384*128+255)/256, 256>>>(Wg, T+T_WG, 128);
    prep_W_kernel<<<(384*64+255)/256, 256>>>(Wc, T+T_WC, 64);
    prep_T_kernel<1,0><<<dim3(NN/64, BB), 256>>>(h0, T+T_H, F+O_HF);

    // ---- s2: x-diffusion slices (need S2 + x transpose), overlap the recurrence ----
    cudaStreamWaitEvent(s2, evS2, 0);
    for (int t = 0; t < TT; t++){
        size_t xo = (size_t)t * MH * NN;
        diffuse_kernel<0><<<dim3(32,4),256,DSM,s2>>>(T+T_X+xo, T+T_A, T+T_XD1+xo, T+T_XD2+xo);
        cudaEventRecord(evX[t], s2);
    }

    // ---- main: the h-chain; cand(t) completion feeds per-step output drain on s2 ----
    for (int t = 0; t < TT; t++){
        diffuse_kernel<0><<<dim3(32,4),256,DSM>>>(T+T_H, T+T_A, T+T_HD1, T+T_HD2);
        cudaStreamWaitEvent(0, evX[t], 0);     // xd(t) ready (also joins fork at t=11)
        gate_mma_kernel<<<dim3(16,8),256,GSM>>>(bg, t);
        diffuse_kernel<0><<<dim3(32,4),256,DSM>>>(T+T_G, T+T_A, T+T_GD1, T+T_GD2);
        cand_mma_kernel<<<dim3(16,8),256,CSM>>>(bc, t);
        cudaEventRecord(evC[t], 0);
    }

    // ---- s2: per-step residual outputs, overlapping later recurrence steps ----
    for (int t = 0; t < TT; t++){
        cudaStreamWaitEvent(s2, evC[t], 0);
        final_out_kernel<<<dim3(NN/64, BB), 256, 0, s2>>>(x, out, t);
    }
    cudaEventRecord(evS2done, s2);

    // ---- main: join + last state ----
    cudaStreamWaitEvent(0, evS2done, 0);
    last_out_kernel<<<dim3(NN/64, BB), 256>>>(out + MXN);
}

// round 16
// speedup vs baseline: 1.4017x; 1.4017x over previous
#include <cuda_runtime.h>
#include <cstdint>
#include <cstddef>

#define NN 2048
#define BB 8
#define TT 12
#define DD 64
#define MX 6144
#define MH 512
static constexpr size_t MXN = (size_t)MX*NN;
static constexpr size_t MHN = (size_t)MH*NN;
static constexpr size_t NN2 = (size_t)NN*NN;

// ---- exact fp32 scratch ----
static constexpr size_t O_ST=0, O_HF=O_ST+12*MHN, O_RF=O_HF+MHN, NFB=O_RF+MHN;
// ---- tf32-rounded scratch (T_S2 MUST follow T_A: stacked [A';S2']) ----
// x / xd buffers are T-MAJOR: row = t*512 + b*64 + d
static constexpr size_t T_A=0, T_S2=T_A+NN2, T_AT=T_S2+NN2, T_X=T_AT+NN2,
 T_XD1=T_X+MXN, T_XD2=T_XD1+MXN,
 T_H=T_XD2+MXN, T_HD1=T_H+MHN, T_HD2=T_HD1+MHN,
 T_G=T_HD2+MHN, T_GD1=T_G+MHN, T_GD2=T_GD1+MHN,
 T_WG=T_GD2+MHN, T_WC=T_WG+384*128, NTB=T_WC+384*64;

__device__ float g_fbuf[NFB];
__device__ float g_tbuf[NTB];

// ---------------- helpers ----------------
__device__ __forceinline__ uint32_t smem_u32(const void* p){
    uint32_t a;
    asm("{ .reg .u64 t; cvta.to.shared.u64 t, %1; cvt.u32.u64 %0, t; }" : "=r"(a) : "l"(p));
    return a;
}
#define SWZ(x) ((x) ^ (((x) >> 3) & 0x70))

__device__ __forceinline__ float tf32r(float v){
    uint32_t r; asm("cvt.rna.tf32.f32 %0, %1;" : "=r"(r) : "f"(v));
    return __uint_as_float(r);
}
__device__ __forceinline__ uint32_t lds_u(uint32_t a){
    uint32_t v; asm volatile("ld.shared.b32 %0, [%1];" : "=r"(v) : "r"(a)); return v;
}
__device__ __forceinline__ void cpa16(uint32_t d, const void* s){
    asm volatile("cp.async.cg.shared.global [%0], [%1], 16;" :: "r"(d), "l"(s) : "memory");
}
__device__ __forceinline__ void mma1688(float* c, const uint32_t* a, uint32_t b0, uint32_t b1){
    asm volatile("mma.sync.aligned.m16n8k8.row.col.f32.tf32.tf32.f32 "
        "{%0,%1,%2,%3}, {%4,%5,%6,%7}, {%8,%9}, {%0,%1,%2,%3};"
        : "+f"(c[0]), "+f"(c[1]), "+f"(c[2]), "+f"(c[3])
        : "r"(a[0]), "r"(a[1]), "r"(a[2]), "r"(a[3]), "r"(b0), "r"(b1));
}

// ---------------- diffusion tile core (tf32): out[m][n] = sum_k act[m][k] * B[n][k] ----------------
// CTA tile 128x128, 8 warps as 2 K-GROUPS x (2m x 2n), warp tile 64x64 -> LDS/MMA = 1.0.
// Group g processes chunk kc+g of each chunk pair; partial accumulators reduced via smem at end.
// K=2048 in 64 chunks. 6 smem stages, pair commit, 1 sync per 2 chunks.
// S2M=1: out1 = tf32(2*v - I). S2M=0: n<NN -> out1, else out2 (at n-NN). Outputs tf32.
template<int S2M>
__device__ __forceinline__ void diffuse_tile(
    const float* __restrict__ actT, const float* __restrict__ bTp,
    float* __restrict__ out1, float* __restrict__ out2,
    int m0, int n0, uint32_t sb)
{
    constexpr int ABYTES = 128 * 128;
    constexpr int STG = ABYTES + 16384;         // 32KB/stage
    int tid = threadIdx.x, lane = tid & 31, wid = tid >> 5;
    int kg = wid >> 2;                          // k-group 0/1
    int wq = wid & 3;                           // quad position within group
    int wm = wq >> 1, wn = wq & 1;              // 2x2, warp tile 64x64

    const char* aT = (const char*)(actT + (size_t)m0 * NN);
    const char* bT = (const char*)(bTp  + (size_t)n0 * NN);

    auto load_chunk = [&](int kc, int stg){
        const char* As = aT + (size_t)kc * 128;
        const char* Bs = bT + (size_t)kc * 128;
        uint32_t s = sb + stg * STG;
        #pragma unroll
        for (int i = 0; i < 4; i++){
            int q = tid + (i << 8);
            int row = q >> 3, c = (q & 7) << 4;
            cpa16(s + SWZ((uint32_t)(row*128 + c)), As + (size_t)row*8192 + c);
        }
        #pragma unroll
        for (int i = 0; i < 4; i++){
            int q = tid + (i << 8);
            int row = q >> 3, c = (q & 7) << 4;
            cpa16(s + ABYTES + SWZ((uint32_t)(row*128 + c)), Bs + (size_t)row*8192 + c);
        }
    };

    float acc[4][8][4];
    #pragma unroll
    for (int i = 0; i < 4; i++)
        #pragma unroll
        for (int j = 0; j < 8; j++)
            #pragma unroll
            for (int q = 0; q < 4; q++) acc[i][j][q] = 0.f;

    load_chunk(0, 0); load_chunk(1, 1);
    asm volatile("cp.async.commit_group;" ::: "memory");
    load_chunk(2, 2); load_chunk(3, 3);
    asm volatile("cp.async.commit_group;" ::: "memory");

    uint32_t af[4][4], bfr[8][2];
    auto load_frags = [&](uint32_t stgBase, int s){
        uint32_t sA = stgBase, sB = stgBase + ABYTES;
        uint32_t c0 = (uint32_t)(s*32 + ((lane & 3) << 2));
        #pragma unroll
        for (int i = 0; i < 4; i++){
            int row = wm*64 + i*16 + (lane >> 2);
            af[i][0] = lds_u(sA + SWZ((uint32_t)(row*128)     + c0));
            af[i][1] = lds_u(sA + SWZ((uint32_t)((row+8)*128) + c0));
            af[i][2] = lds_u(sA + SWZ((uint32_t)(row*128)     + c0 + 16));
            af[i][3] = lds_u(sA + SWZ((uint32_t)((row+8)*128) + c0 + 16));
        }
        #pragma unroll
        for (int j = 0; j < 8; j++){
            int n = wn*64 + j*8 + (lane >> 2);
            bfr[j][0] = lds_u(sB + SWZ((uint32_t)(n*128) + c0));
            bfr[j][1] = lds_u(sB + SWZ((uint32_t)(n*128) + c0 + 16));
        }
    };

    for (int kc = 0; kc < 64; kc += 2){
        asm volatile("cp.async.wait_group 1;" ::: "memory");
        __syncthreads();
        // group kg computes chunk kc+kg from its stage
        uint32_t stg = sb + ((kc + kg) % 6) * STG;
        #pragma unroll
        for (int s = 0; s < 4; s++){
            load_frags(stg, s);
            #pragma unroll
            for (int i = 0; i < 4; i++)
                #pragma unroll
                for (int j = 0; j < 8; j++)
                    mma1688(acc[i][j], af[i], bfr[j][0], bfr[j][1]);
        }
        if (kc + 4 < 64){
            load_chunk(kc + 4, (kc + 4) % 6);
            load_chunk(kc + 5, (kc + 5) % 6);
        }
        asm volatile("cp.async.commit_group;" ::: "memory");
    }

    // ---- split-K reduction: group 1 -> smem (stages 0-1 area, conflict-free layout) ----
    __syncthreads();
    if (kg == 1){
        #pragma unroll
        for (int i = 0; i < 4; i++)
            #pragma unroll
            for (int j = 0; j < 8; j++)
                #pragma unroll
                for (int q = 0; q < 4; q++){
                    int idx = ((i*8 + j) << 2) + q;     // 0..127
                    uint32_t a = sb + (uint32_t)(((idx << 7) + (wq << 5) + lane) << 2);
                    asm volatile("st.shared.f32 [%0], %1;" :: "r"(a), "f"(acc[i][j][q]) : "memory");
                }
    }
    __syncthreads();
    if (kg == 1) return;     // group 1 done

    #pragma unroll
    for (int i = 0; i < 4; i++)
        #pragma unroll
        for (int j = 0; j < 8; j++)
            #pragma unroll
            for (int q = 0; q < 4; q++){
                int idx = ((i*8 + j) << 2) + q;
                uint32_t a = sb + (uint32_t)(((idx << 7) + (wq << 5) + lane) << 2);
                float p; asm volatile("ld.shared.f32 %0, [%1];" : "=f"(p) : "r"(a));
                acc[i][j][q] += p;
            }

    float* o; int cb;
    if (S2M || n0 < NN){ o = out1; cb = n0; }
    else { o = out2; cb = n0 - NN; }
    #pragma unroll
    for (int i = 0; i < 4; i++){
        int rowb = m0 + wm*64 + i*16 + (lane >> 2);
        #pragma unroll
        for (int j = 0; j < 8; j++){
            int col = cb + wn*64 + j*8 + (lane & 3)*2;
            #pragma unroll
            for (int h = 0; h < 2; h++){
                int row = rowb + h*8;
                size_t off = (size_t)row * NN + col;
                float2 v; v.x = acc[i][j][h*2]; v.y = acc[i][j][h*2+1];
                if (S2M){
                    v.x = 2.f*v.x - ((row == col)   ? 1.f : 0.f);
                    v.y = 2.f*v.y - ((row == col+1) ? 1.f : 0.f);
                }
                v.x = tf32r(v.x); v.y = tf32r(v.y);
                *(float2*)&o[off] = v;
            }
        }
    }
}

// standalone diffuse kernel (256 threads)
template<int S2M>
__global__ __launch_bounds__(256)
void diffuse_kernel(const float* __restrict__ actT, const float* __restrict__ bTp,
                    float* __restrict__ out1, float* __restrict__ out2)
{
    extern __shared__ char smem[];
    diffuse_tile<S2M>(actT, bTp, out1, out2, blockIdx.y << 7, blockIdx.x << 7, smem_u32(smem));
}

// ---------------- gate/cand MMA cores (256 threads) ----------------
#define FS_PAD 136
#define FS_B (32*FS_PAD*4)

template<int MO>   // 128 = gate, 64 = cand
__device__ __forceinline__ void gc_mma_core(
    const float* const* srcs, const float* Wt, int n0,
    float acc[2][8][4], int lane, int wm, int wn, uint32_t sb)
{
    constexpr int WSB = MO * 144;
    constexpr int STG = WSB + FS_B;
    constexpr int NJ = (MO == 128) ? 8 : 4;
    int tid = threadIdx.x;

    auto load_chunk = [&](int kc, int stg){
        uint32_t s = sb + stg * STG;
        const float* wsrc = Wt + kc*32;
        #pragma unroll
        for (int i = 0; i < MO*8/256; i++){
            int q = tid + (i << 8);
            int row = q >> 3, c16 = (q & 7) << 4;
            cpa16(s + (uint32_t)(row*144 + c16), (const char*)(wsrc + (size_t)row*384) + c16);
        }
        const float* fsrc = srcs[kc >> 1] + (size_t)((kc & 1) << 5)*NN + n0;
        #pragma unroll
        for (int i = 0; i < 4; i++){
            int q = tid + (i << 8);
            int row = q >> 5, c16 = (q & 31) << 4;
            cpa16(s + WSB + (uint32_t)(row*(FS_PAD*4) + c16), (const char*)(fsrc + (size_t)row*NN) + c16);
        }
    };

    load_chunk(0, 0); asm volatile("cp.async.commit_group;" ::: "memory");
    load_chunk(1, 1); asm volatile("cp.async.commit_group;" ::: "memory");

    for (int kc = 0; kc < 12; kc++){
        asm volatile("cp.async.wait_group 1;" ::: "memory");
        __syncthreads();
        uint32_t sW = sb + (kc % 3) * STG, sF = sW + WSB;
        #pragma unroll
        for (int s = 0; s < 4; s++){
            int k = s*8 + (lane & 3);
            uint32_t a[2][4];
            #pragma unroll
            for (int i = 0; i < 2; i++){
                int row = wm*32 + i*16 + (lane >> 2);
                a[i][0] = lds_u(sW + (uint32_t)(row*144     + k*4));
                a[i][1] = lds_u(sW + (uint32_t)((row+8)*144 + k*4));
                a[i][2] = lds_u(sW + (uint32_t)(row*144     + (k+4)*4));
                a[i][3] = lds_u(sW + (uint32_t)((row+8)*144 + (k+4)*4));
            }
            #pragma unroll
            for (int j = 0; j < NJ; j++){
                int n = wn*(NJ*8) + j*8 + (lane >> 2);
                uint32_t b0 = lds_u(sF + (uint32_t)(k*(FS_PAD*4)     + n*4));
                uint32_t b1 = lds_u(sF + (uint32_t)((k+4)*(FS_PAD*4) + n*4));
                mma1688(acc[0][j], a[0], b0, b1);
                mma1688(acc[1][j], a[1], b0, b1);
            }
        }
        if (kc + 2 < 12) load_chunk(kc + 2, (kc + 2) % 3);
        asm volatile("cp.async.commit_group;" ::: "memory");
    }
}

__global__ __launch_bounds__(256)
void gate_mma_kernel(const float* __restrict__ bg, int t){
    extern __shared__ char smem[];
    uint32_t sb = smem_u32(smem);
    int tid = threadIdx.x, lane = tid & 31, wid = tid >> 5;
    int wm = wid >> 1, wn = wid & 1;
    int n0 = blockIdx.x << 7, b = blockIdx.y;
    // x/xd buffers t-major: row base = t*512 + b*64
    const float* srcs[6] = {
        g_tbuf + T_X   + ((size_t)t*MH + b*DD)*NN,
        g_tbuf + T_H   + (size_t)b*DD*NN,
        g_tbuf + T_XD1 + ((size_t)t*MH + b*DD)*NN,
        g_tbuf + T_HD1 + (size_t)b*DD*NN,
        g_tbuf + T_XD2 + ((size_t)t*MH + b*DD)*NN,
        g_tbuf + T_HD2 + (size_t)b*DD*NN };
    float acc[2][8][4];
    #pragma unroll
    for (int i=0;i<2;i++) for (int j=0;j<8;j++) for (int q=0;q<4;q++) acc[i][j][q]=0.f;
    gc_mma_core<128>(srcs, g_tbuf + T_WG, n0, acc, lane, wm, wn, sb);

    #pragma unroll
    for (int i = 0; i < 2; i++){
        int ob = wm*32 + i*16 + (lane >> 2);
        #pragma unroll
        for (int j = 0; j < 8; j++){
            int n = n0 + wn*64 + j*8 + (lane & 3)*2;
            #pragma unroll
            for (int h = 0; h < 2; h++){
                int o = ob + h*8;
                float2 v; v.x = acc[i][j][h*2] + bg[o]; v.y = acc[i][j][h*2+1] + bg[o];
                v.x = 1.f/(1.f + __expf(-v.x)); v.y = 1.f/(1.f + __expf(-v.y));
                if (o < 64){
                    size_t idx = ((size_t)b*DD + o)*NN + n;
                    float2 hh = *(const float2*)&g_fbuf[O_HF + idx];
                    float2 g; g.x = tf32r(v.x*hh.x); g.y = tf32r(v.y*hh.y);
                    *(float2*)&g_tbuf[T_G + idx] = g;
                } else {
                    *(float2*)&g_fbuf[O_RF + ((size_t)b*DD + (o-64))*NN + n] = v;
                }
            }
        }
    }
}

__global__ __launch_bounds__(256)
void cand_mma_kernel(const float* __restrict__ bc, int t){
    extern __shared__ char smem[];
    uint32_t sb = smem_u32(smem);
    int tid = threadIdx.x, lane = tid & 31, wid = tid >> 5;
    int wm = wid >> 2, wn = wid & 3;
    int n0 = blockIdx.x << 7, b = blockIdx.y;
    const float* srcs[6] = {
        g_tbuf + T_X   + ((size_t)t*MH + b*DD)*NN,
        g_tbuf + T_G   + (size_t)b*DD*NN,
        g_tbuf + T_XD1 + ((size_t)t*MH + b*DD)*NN,
        g_tbuf + T_GD1 + (size_t)b*DD*NN,
        g_tbuf + T_XD2 + ((size_t)t*MH + b*DD)*NN,
        g_tbuf + T_GD2 + (size_t)b*DD*NN };
    float acc[2][8][4];
    #pragma unroll
    for (int i=0;i<2;i++) for (int j=0;j<8;j++) for (int q=0;q<4;q++) acc[i][j][q]=0.f;
    gc_mma_core<64>(srcs, g_tbuf + T_WC, n0, acc, lane, wm, wn, sb);

    #pragma unroll
    for (int i = 0; i < 2; i++){
        int ob = wm*32 + i*16 + (lane >> 2);
        #pragma unroll
        for (int j = 0; j < 4; j++){
            int n = n0 + wn*32 + j*8 + (lane & 3)*2;
            #pragma unroll
            for (int h = 0; h < 2; h++){
                int o = ob + h*8;
                size_t idx = ((size_t)b*DD + o)*NN + n;
                float2 hc; hc.x = tanhf(acc[i][j][h*2] + bc[o]); hc.y = tanhf(acc[i][j][h*2+1] + bc[o]);
                float2 r  = *(const float2*)&g_fbuf[O_RF + idx];
                float2 hh = *(const float2*)&g_fbuf[O_HF + idx];
                float2 hn; hn.x = r.x*hh.x + (1.f-r.x)*hc.x; hn.y = r.y*hh.y + (1.f-r.y)*hc.y;
                *(float2*)&g_fbuf[O_HF + idx] = hn;
                float2 ht; ht.x = tf32r(hn.x); ht.y = tf32r(hn.y);
                *(float2*)&g_tbuf[T_H + idx] = ht;
                *(float2*)&g_fbuf[O_ST + (size_t)t*MHN + idx] = hn;
            }
        }
    }
}

// ---------------- prep kernels ----------------
__global__ __launch_bounds__(256) void prep_adj_kernel(const float* __restrict__ adj){
    size_t i = ((size_t)blockIdx.x * 256 + threadIdx.x) * 4;
    float4 v = *(const float4*)&adj[i];
    float4 t; t.x = tf32r(v.x); t.y = tf32r(v.y); t.z = tf32r(v.z); t.w = tf32r(v.w);
    *(float4*)&g_tbuf[T_A + i] = t;
}

__global__ __launch_bounds__(256) void prep_adjT_kernel(const float* __restrict__ adj){
    __shared__ float S[32][33];
    int x0 = blockIdx.x << 5, y0 = blockIdx.y << 5;
    int tx = threadIdx.x & 31, ty = threadIdx.x >> 5;
    #pragma unroll
    for (int i = 0; i < 4; i++)
        S[ty + i*8][tx] = adj[(size_t)(y0 + ty + i*8)*NN + x0 + tx];
    __syncthreads();
    #pragma unroll
    for (int i = 0; i < 4; i++)
        g_tbuf[T_AT + (size_t)(x0 + ty + i*8)*NN + y0 + tx] = tf32r(S[tx][ty + i*8]);
}

__global__ void prep_W_kernel(const float* __restrict__ W, float* __restrict__ Wt, int O){
    int i = blockIdx.x * 256 + threadIdx.x;
    if (i >= 384*O) return;
    int k = i / O, o = i % O;
    Wt[(size_t)o*384 + k] = tf32r(W[i]);
}

// transpose [rr][n][d] -> feature-major rows. XMAJ=1: rr=b*TT+t -> dest row (t*BB+b)*64+d.
template<int WF, int XMAJ>
__global__ __launch_bounds__(256)
void prep_T_kernel(const float* __restrict__ src, float* __restrict__ dstT,
                   float* __restrict__ dstF){
    __shared__ float S[64][65];
    int n0 = blockIdx.x << 6, rr = blockIdx.y;
    int rdest = XMAJ ? ((rr % TT) * BB + rr / TT) : rr;
    const float* sp = src + ((size_t)rr * NN + n0) * DD;
    #pragma unroll
    for (int i = 0; i < 16; i++){
        int q = threadIdx.x + (i << 8);
        S[q >> 6][q & 63] = sp[(size_t)(q >> 6) * DD + (q & 63)];
    }
    __syncthreads();
    #pragma unroll
    for (int i = 0; i < 16; i++){
        int q = threadIdx.x + (i << 8);
        int d = q >> 6, nl = q & 63;
        float v = S[nl][d];
        size_t off = ((size_t)rdest * DD + d) * NN + n0 + nl;
        dstT[off] = tf32r(v);
        if (WF) dstF[off] = v;
    }
}

// ---------------- output assembly ----------------
__global__ __launch_bounds__(256)
void final_out_kernel(const float* __restrict__ x, float* __restrict__ out){
    __shared__ float S[64][65];
    int n0 = blockIdx.x << 6, bt = blockIdx.y;
    int b = bt / TT, t = bt % TT;
    const float* st = g_fbuf + O_ST + (size_t)t*MHN + (size_t)b*DD*NN;
    #pragma unroll
    for (int i = 0; i < 16; i++){
        int q = threadIdx.x + (i << 8);
        int d = q >> 6, nl = q & 63;
        S[d][nl] = st[(size_t)d*NN + n0 + nl];
    }
    __syncthreads();
    #pragma unroll
    for (int i = 0; i < 16; i++){
        int q = threadIdx.x + (i << 8);
        int nl = q >> 6, d = q & 63;
        size_t off = ((size_t)bt*NN + n0 + nl)*DD + d;
        out[off] = x[off] + S[d][nl];
    }
}

__global__ __launch_bounds__(256)
void last_out_kernel(float* __restrict__ outL){
    __shared__ float S[64][65];
    int n0 = blockIdx.x << 6, b = blockIdx.y;
    const float* hp = g_fbuf + O_HF + (size_t)b*DD*NN;
    #pragma unroll
    for (int i = 0; i < 16; i++){
        int q = threadIdx.x + (i << 8);
        int d = q >> 6, nl = q & 63;
        S[d][nl] = hp[(size_t)d*NN + n0 + nl];
    }
    __syncthreads();
    #pragma unroll
    for (int i = 0; i < 16; i++){
        int q = threadIdx.x + (i << 8);
        int nl = q >> 6, d = q & 63;
        outL[((size_t)b*NN + n0 + nl)*DD + d] = S[d][nl];
    }
}

// ---------------- launch (R13 topology exactly) ----------------
extern "C" void kernel_launch(void* const* d_in, const int* in_sizes, int n_in,
                              void* d_out, int out_size) {
    const float* x   = (const float*)d_in[0];
    const float* h0  = (const float*)d_in[1];
    const float* adj = (const float*)d_in[2];
    const float* Wg  = (const float*)d_in[3];
    const float* bg  = (const float*)d_in[4];
    const float* Wc  = (const float*)d_in[5];
    const float* bc  = (const float*)d_in[6];
    float* out = (float*)d_out;

    void *pf, *pt;
    cudaGetSymbolAddress(&pf, g_fbuf);
    cudaGetSymbolAddress(&pt, g_tbuf);
    float* F = (float*)pf;
    float* T = (float*)pt;

    const int DSM = 6 * 32768;                    // 196608 bytes
    const int GSM = 3 * (128*144 + FS_B);
    const int CSM = 3 * (64*144  + FS_B);
    cudaFuncSetAttribute(diffuse_kernel<0>, cudaFuncAttributeMaxDynamicSharedMemorySize, DSM);
    cudaFuncSetAttribute(diffuse_kernel<1>, cudaFuncAttributeMaxDynamicSharedMemorySize, DSM);
    cudaFuncSetAttribute(gate_mma_kernel,   cudaFuncAttributeMaxDynamicSharedMemorySize, GSM);
    cudaFuncSetAttribute(cand_mma_kernel,   cudaFuncAttributeMaxDynamicSharedMemorySize, CSM);

    // fork stream + events (host objects; created fresh each call, leaked — 2 calls total)
    cudaStream_t s2;
    cudaStreamCreateWithFlags(&s2, cudaStreamNonBlocking);
    cudaEvent_t evFork, evX[TT];
    cudaEventCreateWithFlags(&evFork, cudaEventDisableTiming);
    for (int t = 0; t < TT; t++) cudaEventCreateWithFlags(&evX[t], cudaEventDisableTiming);

    // ---- main stream: shared prep (A', A'^T, S2', x transposed) ----
    prep_adj_kernel<<<(int)(NN2/1024), 256>>>(adj);
    prep_adjT_kernel<<<dim3(NN/32, NN/32), 256>>>(adj);
    prep_T_kernel<0,1><<<dim3(NN/64, BB*TT), 256>>>(x,  T+T_X, nullptr);   // x -> t-major
    diffuse_kernel<1><<<dim3(16,16),256,DSM>>>(T+T_A, T+T_AT, T+T_S2, nullptr);  // S2'

    // ---- fork: x-diffusion slices run concurrently with the recurrence ----
    cudaEventRecord(evFork, 0);
    cudaStreamWaitEvent(s2, evFork, 0);
    for (int t = 0; t < TT; t++){
        size_t xo = (size_t)t * MH * NN;
        diffuse_kernel<0><<<dim3(32,4),256,DSM,s2>>>(T+T_X+xo, T+T_A, T+T_XD1+xo, T+T_XD2+xo);
        cudaEventRecord(evX[t], s2);
    }

    // ---- main stream: recurrence-only prep, then the h-chain ----
    prep_W_kernel<<<(384*128+255)/256, 256>>>(Wg, T+T_WG, 128);
    prep_W_kernel<<<(384*64+255)/256, 256>>>(Wc, T+T_WC, 64);
    prep_T_kernel<1,0><<<dim3(NN/64, BB), 256>>>(h0, T+T_H, F+O_HF);

    for (int t = 0; t < TT; t++){
        diffuse_kernel<0><<<dim3(32,4),256,DSM>>>(T+T_H, T+T_A, T+T_HD1, T+T_HD2);
        cudaStreamWaitEvent(0, evX[t], 0);     // xd(t) ready (also joins fork at t=11)
        gate_mma_kernel<<<dim3(16,8),256,GSM>>>(bg, t);
        diffuse_kernel<0><<<dim3(32,4),256,DSM>>>(T+T_G, T+T_A, T+T_GD1, T+T_GD2);
        cand_mma_kernel<<<dim3(16,8),256,CSM>>>(bc, t);
    }

    final_out_kernel<<<dim3(NN/64, BB*TT), 256>>>(x, out);
    last_out_kernel<<<dim3(NN/64, BB), 256>>>(out + MXN);
}

// round 17
// speedup vs baseline: 1.4868x; 1.0607x over previous
#include <cuda_runtime.h>
#include <cstdint>
#include <cstddef>

#define NN 2048
#define BB 8
#define TT 12
#define DD 64
#define MX 6144
#define MH 512
static constexpr size_t MXN = (size_t)MX*NN;
static constexpr size_t MHN = (size_t)MH*NN;
static constexpr size_t NN2 = (size_t)NN*NN;

// ---- exact fp32 scratch ----
static constexpr size_t O_ST=0, O_HF=O_ST+12*MHN, O_RF=O_HF+MHN,
 O_PG=O_RF+MHN,                         // gate x-partials [t][b][128][NN]
 O_PC=O_PG+(size_t)TT*BB*128*NN,        // cand x-partials [t][b][64][NN]
 NFB=O_PC+(size_t)TT*BB*64*NN;
// ---- tf32-rounded scratch (T_S2 MUST follow T_A: stacked [A';S2']) ----
// x / xd buffers are T-MAJOR: row = t*512 + b*64 + d
static constexpr size_t T_A=0, T_S2=T_A+NN2, T_AT=T_S2+NN2, T_X=T_AT+NN2,
 T_XD1=T_X+MXN, T_XD2=T_XD1+MXN,
 T_H=T_XD2+MXN, T_HD1=T_H+MHN, T_HD2=T_HD1+MHN,
 T_G=T_HD2+MHN, T_GD1=T_G+MHN, T_GD2=T_GD1+MHN,
 T_WG=T_GD2+MHN, T_WC=T_WG+384*128, NTB=T_WC+384*64;

__device__ float g_fbuf[NFB];
__device__ float g_tbuf[NTB];

// ---------------- helpers ----------------
__device__ __forceinline__ uint32_t smem_u32(const void* p){
    uint32_t a;
    asm("{ .reg .u64 t; cvta.to.shared.u64 t, %1; cvt.u32.u64 %0, t; }" : "=r"(a) : "l"(p));
    return a;
}
#define SWZ(x) ((x) ^ (((x) >> 3) & 0x70))

__device__ __forceinline__ float tf32r(float v){
    uint32_t r; asm("cvt.rna.tf32.f32 %0, %1;" : "=r"(r) : "f"(v));
    return __uint_as_float(r);
}
__device__ __forceinline__ uint32_t lds_u(uint32_t a){
    uint32_t v; asm volatile("ld.shared.b32 %0, [%1];" : "=r"(v) : "r"(a)); return v;
}
__device__ __forceinline__ void cpa16(uint32_t d, const void* s){
    asm volatile("cp.async.cg.shared.global [%0], [%1], 16;" :: "r"(d), "l"(s) : "memory");
}
__device__ __forceinline__ void mma1688(float* c, const uint32_t* a, uint32_t b0, uint32_t b1){
    asm volatile("mma.sync.aligned.m16n8k8.row.col.f32.tf32.tf32.f32 "
        "{%0,%1,%2,%3}, {%4,%5,%6,%7}, {%8,%9}, {%0,%1,%2,%3};"
        : "+f"(c[0]), "+f"(c[1]), "+f"(c[2]), "+f"(c[3])
        : "r"(a[0]), "r"(a[1]), "r"(a[2]), "r"(a[3]), "r"(b0), "r"(b1));
}

// ---------------- diffusion tile core (R13 exact): out[m][n] = sum_k act[m][k]*B[n][k] ----------------
template<int S2M>
__device__ __forceinline__ void diffuse_tile(
    const float* __restrict__ actT, const float* __restrict__ bTp,
    float* __restrict__ out1, float* __restrict__ out2,
    int m0, int n0, uint32_t sb)
{
    constexpr int ABYTES = 128 * 128;
    constexpr int STG = ABYTES + 16384;         // 32KB/stage
    int tid = threadIdx.x, lane = tid & 31, wid = tid >> 5;
    int wm = wid >> 1, wn = wid & 1;

    const char* aT = (const char*)(actT + (size_t)m0 * NN);
    const char* bT = (const char*)(bTp  + (size_t)n0 * NN);

    auto load_chunk = [&](int kc, int stg){
        const char* As = aT + (size_t)kc * 128;
        const char* Bs = bT + (size_t)kc * 128;
        uint32_t s = sb + stg * STG;
        #pragma unroll
        for (int i = 0; i < 4; i++){
            int q = tid + (i << 8);
            int row = q >> 3, c = (q & 7) << 4;
            cpa16(s + SWZ((uint32_t)(row*128 + c)), As + (size_t)row*8192 + c);
        }
        #pragma unroll
        for (int i = 0; i < 4; i++){
            int q = tid + (i << 8);
            int row = q >> 3, c = (q & 7) << 4;
            cpa16(s + ABYTES + SWZ((uint32_t)(row*128 + c)), Bs + (size_t)row*8192 + c);
        }
    };

    float acc[2][8][4];
    #pragma unroll
    for (int i = 0; i < 2; i++)
        #pragma unroll
        for (int j = 0; j < 8; j++)
            #pragma unroll
            for (int q = 0; q < 4; q++) acc[i][j][q] = 0.f;

    load_chunk(0, 0); load_chunk(1, 1);
    asm volatile("cp.async.commit_group;" ::: "memory");
    load_chunk(2, 2); load_chunk(3, 3);
    asm volatile("cp.async.commit_group;" ::: "memory");

    uint32_t af[2][2][4], bfr[2][8][2];
    auto load_frags = [&](uint32_t stgBase, int s, int buf){
        uint32_t sA = stgBase, sB = stgBase + ABYTES;
        uint32_t c0 = (uint32_t)(s*32 + ((lane & 3) << 2));
        #pragma unroll
        for (int i = 0; i < 2; i++){
            int row = wm*32 + i*16 + (lane >> 2);
            af[buf][i][0] = lds_u(sA + SWZ((uint32_t)(row*128)     + c0));
            af[buf][i][1] = lds_u(sA + SWZ((uint32_t)((row+8)*128) + c0));
            af[buf][i][2] = lds_u(sA + SWZ((uint32_t)(row*128)     + c0 + 16));
            af[buf][i][3] = lds_u(sA + SWZ((uint32_t)((row+8)*128) + c0 + 16));
        }
        #pragma unroll
        for (int j = 0; j < 8; j++){
            int n = wn*64 + j*8 + (lane >> 2);
            bfr[buf][j][0] = lds_u(sB + SWZ((uint32_t)(n*128) + c0));
            bfr[buf][j][1] = lds_u(sB + SWZ((uint32_t)(n*128) + c0 + 16));
        }
    };

    for (int kc = 0; kc < 64; kc += 2){
        asm volatile("cp.async.wait_group 1;" ::: "memory");
        __syncthreads();
        uint32_t st0 = sb + (kc % 6) * STG;
        uint32_t st1 = sb + ((kc + 1) % 6) * STG;

        load_frags(st0, 0, 0);
        #pragma unroll
        for (int s = 0; s < 8; s++){
            if (s < 7){
                int sn = s + 1;
                load_frags((sn < 4) ? st0 : st1, sn & 3, sn & 1);
            }
            int b = s & 1;
            #pragma unroll
            for (int j = 0; j < 8; j++){
                mma1688(acc[0][j], af[b][0], bfr[b][j][0], bfr[b][j][1]);
                mma1688(acc[1][j], af[b][1], bfr[b][j][0], bfr[b][j][1]);
            }
        }
        if (kc + 4 < 64){
            load_chunk(kc + 4, (kc + 4) % 6);
            load_chunk(kc + 5, (kc + 5) % 6);
        }
        asm volatile("cp.async.commit_group;" ::: "memory");
    }

    float* o; int cb;
    if (S2M || n0 < NN){ o = out1; cb = n0; }
    else { o = out2; cb = n0 - NN; }
    #pragma unroll
    for (int i = 0; i < 2; i++){
        int rowb = m0 + wm*32 + i*16 + (lane >> 2);
        #pragma unroll
        for (int j = 0; j < 8; j++){
            int col = cb + wn*64 + j*8 + (lane & 3)*2;
            #pragma unroll
            for (int h = 0; h < 2; h++){
                int row = rowb + h*8;
                size_t off = (size_t)row * NN + col;
                float2 v; v.x = acc[i][j][h*2]; v.y = acc[i][j][h*2+1];
                if (S2M){
                    v.x = 2.f*v.x - ((row == col)   ? 1.f : 0.f);
                    v.y = 2.f*v.y - ((row == col+1) ? 1.f : 0.f);
                }
                v.x = tf32r(v.x); v.y = tf32r(v.y);
                *(float2*)&o[off] = v;
            }
        }
    }
}

template<int S2M>
__global__ __launch_bounds__(256)
void diffuse_kernel(const float* __restrict__ actT, const float* __restrict__ bTp,
                    float* __restrict__ out1, float* __restrict__ out2)
{
    extern __shared__ char smem[];
    diffuse_tile<S2M>(actT, bTp, out1, out2, blockIdx.y << 7, blockIdx.x << 7, smem_u32(smem));
}

// ---------------- gate/cand MMA core: K = NCH*32 chunks, W rows picked by wk[] ----------------
#define FS_PAD 136
#define FS_B (32*FS_PAD*4)

template<int MO, int NCH>
__device__ __forceinline__ void gc_mma_core(
    const float* const* srcs, const float* Wt, const int* wk, int n0,
    float acc[2][8][4], int lane, int wm, int wn, uint32_t sb)
{
    constexpr int WSB = MO * 144;
    constexpr int STG = WSB + FS_B;
    constexpr int NJ = (MO == 128) ? 8 : 4;
    int tid = threadIdx.x;

    auto load_chunk = [&](int kc, int stg){
        uint32_t s = sb + stg * STG;
        const float* wsrc = Wt + wk[kc]*32;
        #pragma unroll
        for (int i = 0; i < MO*8/256; i++){
            int q = tid + (i << 8);
            int row = q >> 3, c16 = (q & 7) << 4;
            cpa16(s + (uint32_t)(row*144 + c16), (const char*)(wsrc + (size_t)row*384) + c16);
        }
        const float* fsrc = srcs[kc >> 1] + (size_t)((kc & 1) << 5)*NN + n0;
        #pragma unroll
        for (int i = 0; i < 4; i++){
            int q = tid + (i << 8);
            int row = q >> 5, c16 = (q & 31) << 4;
            cpa16(s + WSB + (uint32_t)(row*(FS_PAD*4) + c16), (const char*)(fsrc + (size_t)row*NN) + c16);
        }
    };

    load_chunk(0, 0); asm volatile("cp.async.commit_group;" ::: "memory");
    load_chunk(1, 1); asm volatile("cp.async.commit_group;" ::: "memory");

    for (int kc = 0; kc < NCH; kc++){
        asm volatile("cp.async.wait_group 1;" ::: "memory");
        __syncthreads();
        uint32_t sW = sb + (kc % 3) * STG, sF = sW + WSB;
        #pragma unroll
        for (int s = 0; s < 4; s++){
            int k = s*8 + (lane & 3);
            uint32_t a[2][4];
            #pragma unroll
            for (int i = 0; i < 2; i++){
                int row = wm*32 + i*16 + (lane >> 2);
                a[i][0] = lds_u(sW + (uint32_t)(row*144     + k*4));
                a[i][1] = lds_u(sW + (uint32_t)((row+8)*144 + k*4));
                a[i][2] = lds_u(sW + (uint32_t)(row*144     + (k+4)*4));
                a[i][3] = lds_u(sW + (uint32_t)((row+8)*144 + (k+4)*4));
            }
            #pragma unroll
            for (int j = 0; j < NJ; j++){
                int n = wn*(NJ*8) + j*8 + (lane >> 2);
                uint32_t b0 = lds_u(sF + (uint32_t)(k*(FS_PAD*4)     + n*4));
                uint32_t b1 = lds_u(sF + (uint32_t)((k+4)*(FS_PAD*4) + n*4));
                mma1688(acc[0][j], a[0], b0, b1);
                mma1688(acc[1][j], a[1], b0, b1);
            }
        }
        if (kc + 2 < NCH) load_chunk(kc + 2, (kc + 2) % 3);
        asm volatile("cp.async.commit_group;" ::: "memory");
    }
}

__device__ const int WK_X[6] = {0,1,4,5,8,9};     // x, xd1, xd2 halves
__device__ const int WK_H[6] = {2,3,6,7,10,11};   // h, hd1/gd1, hd2/gd2 halves

// ---------------- x-partial kernels (run on s2) ----------------
template<int MO>
__global__ __launch_bounds__(256)
void gcx_kernel(int t){
    extern __shared__ char smem[];
    uint32_t sb = smem_u32(smem);
    int lane = threadIdx.x & 31, wid = threadIdx.x >> 5;
    int wm, wn; if (MO == 128){ wm = wid >> 1; wn = wid & 1; } else { wm = wid >> 2; wn = wid & 3; }
    constexpr int NJ = (MO == 128) ? 8 : 4;
    int n0 = blockIdx.x << 7, b = blockIdx.y;
    const float* srcs[3] = {
        g_tbuf + T_X   + ((size_t)t*MH + b*DD)*NN,
        g_tbuf + T_XD1 + ((size_t)t*MH + b*DD)*NN,
        g_tbuf + T_XD2 + ((size_t)t*MH + b*DD)*NN };
    float acc[2][8][4];
    #pragma unroll
    for (int i=0;i<2;i++) for (int j=0;j<8;j++) for (int q=0;q<4;q++) acc[i][j][q]=0.f;
    gc_mma_core<MO,6>(srcs, g_tbuf + ((MO==128)?T_WG:T_WC), WK_X, n0, acc, lane, wm, wn, sb);

    float* P = g_fbuf + ((MO==128) ? O_PG : O_PC) + ((size_t)t*BB + b)*MO*NN;
    #pragma unroll
    for (int i = 0; i < 2; i++){
        int ob = wm*32 + i*16 + (lane >> 2);
        #pragma unroll
        for (int j = 0; j < NJ; j++){
            int n = n0 + wn*(NJ*8) + j*8 + (lane & 3)*2;
            #pragma unroll
            for (int h = 0; h < 2; h++){
                int o = ob + h*8;
                float2 v; v.x = acc[i][j][h*2]; v.y = acc[i][j][h*2+1];
                *(float2*)&P[(size_t)o*NN + n] = v;
            }
        }
    }
}

// ---------------- main gate/cand (K=192, acc init from partials) ----------------
__global__ __launch_bounds__(256)
void gate_mma_kernel(const float* __restrict__ bg, int t){
    extern __shared__ char smem[];
    uint32_t sb = smem_u32(smem);
    int lane = threadIdx.x & 31, wid = threadIdx.x >> 5;
    int wm = wid >> 1, wn = wid & 1;
    int n0 = blockIdx.x << 7, b = blockIdx.y;
    const float* srcs[3] = {
        g_tbuf + T_H   + (size_t)b*DD*NN,
        g_tbuf + T_HD1 + (size_t)b*DD*NN,
        g_tbuf + T_HD2 + (size_t)b*DD*NN };
    const float* P = g_fbuf + O_PG + ((size_t)t*BB + b)*128*NN;
    float acc[2][8][4];
    #pragma unroll
    for (int i = 0; i < 2; i++){
        int ob = wm*32 + i*16 + (lane >> 2);
        #pragma unroll
        for (int j = 0; j < 8; j++){
            int n = n0 + wn*64 + j*8 + (lane & 3)*2;
            #pragma unroll
            for (int h = 0; h < 2; h++){
                float2 p = *(const float2*)&P[(size_t)(ob + h*8)*NN + n];
                acc[i][j][h*2] = p.x; acc[i][j][h*2+1] = p.y;
            }
        }
    }
    gc_mma_core<128,6>(srcs, g_tbuf + T_WG, WK_H, n0, acc, lane, wm, wn, sb);

    #pragma unroll
    for (int i = 0; i < 2; i++){
        int ob = wm*32 + i*16 + (lane >> 2);
        #pragma unroll
        for (int j = 0; j < 8; j++){
            int n = n0 + wn*64 + j*8 + (lane & 3)*2;
            #pragma unroll
            for (int h = 0; h < 2; h++){
                int o = ob + h*8;
                float2 v; v.x = acc[i][j][h*2] + bg[o]; v.y = acc[i][j][h*2+1] + bg[o];
                v.x = 1.f/(1.f + __expf(-v.x)); v.y = 1.f/(1.f + __expf(-v.y));
                if (o < 64){
                    size_t idx = ((size_t)b*DD + o)*NN + n;
                    float2 hh = *(const float2*)&g_fbuf[O_HF + idx];
                    float2 g; g.x = tf32r(v.x*hh.x); g.y = tf32r(v.y*hh.y);
                    *(float2*)&g_tbuf[T_G + idx] = g;
                } else {
                    *(float2*)&g_fbuf[O_RF + ((size_t)b*DD + (o-64))*NN + n] = v;
                }
            }
        }
    }
}

__global__ __launch_bounds__(256)
void cand_mma_kernel(const float* __restrict__ bc, int t){
    extern __shared__ char smem[];
    uint32_t sb = smem_u32(smem);
    int lane = threadIdx.x & 31, wid = threadIdx.x >> 5;
    int wm = wid >> 2, wn = wid & 3;
    int n0 = blockIdx.x << 7, b = blockIdx.y;
    const float* srcs[3] = {
        g_tbuf + T_G   + (size_t)b*DD*NN,
        g_tbuf + T_GD1 + (size_t)b*DD*NN,
        g_tbuf + T_GD2 + (size_t)b*DD*NN };
    const float* P = g_fbuf + O_PC + ((size_t)t*BB + b)*64*NN;
    float acc[2][8][4];
    #pragma unroll
    for (int i = 0; i < 2; i++){
        int ob = wm*32 + i*16 + (lane >> 2);
        #pragma unroll
        for (int j = 0; j < 4; j++){
            int n = n0 + wn*32 + j*8 + (lane & 3)*2;
            #pragma unroll
            for (int h = 0; h < 2; h++){
                float2 p = *(const float2*)&P[(size_t)(ob + h*8)*NN + n];
                acc[i][j][h*2] = p.x; acc[i][j][h*2+1] = p.y;
            }
        }
    }
    gc_mma_core<64,6>(srcs, g_tbuf + T_WC, WK_H, n0, acc, lane, wm, wn, sb);

    #pragma unroll
    for (int i = 0; i < 2; i++){
        int ob = wm*32 + i*16 + (lane >> 2);
        #pragma unroll
        for (int j = 0; j < 4; j++){
            int n = n0 + wn*32 + j*8 + (lane & 3)*2;
            #pragma unroll
            for (int h = 0; h < 2; h++){
                int o = ob + h*8;
                size_t idx = ((size_t)b*DD + o)*NN + n;
                float2 hc; hc.x = tanhf(acc[i][j][h*2] + bc[o]); hc.y = tanhf(acc[i][j][h*2+1] + bc[o]);
                float2 r  = *(const float2*)&g_fbuf[O_RF + idx];
                float2 hh = *(const float2*)&g_fbuf[O_HF + idx];
                float2 hn; hn.x = r.x*hh.x + (1.f-r.x)*hc.x; hn.y = r.y*hh.y + (1.f-r.y)*hc.y;
                *(float2*)&g_fbuf[O_HF + idx] = hn;
                float2 ht; ht.x = tf32r(hn.x); ht.y = tf32r(hn.y);
                *(float2*)&g_tbuf[T_H + idx] = ht;
                *(float2*)&g_fbuf[O_ST + (size_t)t*MHN + idx] = hn;
            }
        }
    }
}

// ---------------- prep kernels ----------------
__global__ __launch_bounds__(256) void prep_adj_kernel(const float* __restrict__ adj){
    size_t i = ((size_t)blockIdx.x * 256 + threadIdx.x) * 4;
    float4 v = *(const float4*)&adj[i];
    float4 t; t.x = tf32r(v.x); t.y = tf32r(v.y); t.z = tf32r(v.z); t.w = tf32r(v.w);
    *(float4*)&g_tbuf[T_A + i] = t;
}

__global__ __launch_bounds__(256) void prep_adjT_kernel(const float* __restrict__ adj){
    __shared__ float S[32][33];
    int x0 = blockIdx.x << 5, y0 = blockIdx.y << 5;
    int tx = threadIdx.x & 31, ty = threadIdx.x >> 5;
    #pragma unroll
    for (int i = 0; i < 4; i++)
        S[ty + i*8][tx] = adj[(size_t)(y0 + ty + i*8)*NN + x0 + tx];
    __syncthreads();
    #pragma unroll
    for (int i = 0; i < 4; i++)
        g_tbuf[T_AT + (size_t)(x0 + ty + i*8)*NN + y0 + tx] = tf32r(S[tx][ty + i*8]);
}

__global__ void prep_W_kernel(const float* __restrict__ W, float* __restrict__ Wt, int O){
    int i = blockIdx.x * 256 + threadIdx.x;
    if (i >= 384*O) return;
    int k = i / O, o = i % O;
    Wt[(size_t)o*384 + k] = tf32r(W[i]);
}

template<int WF, int XMAJ>
__global__ __launch_bounds__(256)
void prep_T_kernel(const float* __restrict__ src, float* __restrict__ dstT,
                   float* __restrict__ dstF){
    __shared__ float S[64][65];
    int n0 = blockIdx.x << 6, rr = blockIdx.y;
    int rdest = XMAJ ? ((rr % TT) * BB + rr / TT) : rr;
    const float* sp = src + ((size_t)rr * NN + n0) * DD;
    #pragma unroll
    for (int i = 0; i < 16; i++){
        int q = threadIdx.x + (i << 8);
        S[q >> 6][q & 63] = sp[(size_t)(q >> 6) * DD + (q & 63)];
    }
    __syncthreads();
    #pragma unroll
    for (int i = 0; i < 16; i++){
        int q = threadIdx.x + (i << 8);
        int d = q >> 6, nl = q & 63;
        float v = S[nl][d];
        size_t off = ((size_t)rdest * DD + d) * NN + n0 + nl;
        dstT[off] = tf32r(v);
        if (WF) dstF[off] = v;
    }
}

// ---------------- output assembly ----------------
__global__ __launch_bounds__(256)
void final_out_kernel(const float* __restrict__ x, float* __restrict__ out){
    __shared__ float S[64][65];
    int n0 = blockIdx.x << 6, bt = blockIdx.y;
    int b = bt / TT, t = bt % TT;
    const float* st = g_fbuf + O_ST + (size_t)t*MHN + (size_t)b*DD*NN;
    #pragma unroll
    for (int i = 0; i < 16; i++){
        int q = threadIdx.x + (i << 8);
        int d = q >> 6, nl = q & 63;
        S[d][nl] = st[(size_t)d*NN + n0 + nl];
    }
    __syncthreads();
    #pragma unroll
    for (int i = 0; i < 16; i++){
        int q = threadIdx.x + (i << 8);
        int nl = q >> 6, d = q & 63;
        size_t off = ((size_t)bt*NN + n0 + nl)*DD + d;
        out[off] = x[off] + S[d][nl];
    }
}

__global__ __launch_bounds__(256)
void last_out_kernel(float* __restrict__ outL){
    __shared__ float S[64][65];
    int n0 = blockIdx.x << 6, b = blockIdx.y;
    const float* hp = g_fbuf + O_HF + (size_t)b*DD*NN;
    #pragma unroll
    for (int i = 0; i < 16; i++){
        int q = threadIdx.x + (i << 8);
        int d = q >> 6, nl = q & 63;
        S[d][nl] = hp[(size_t)d*NN + n0 + nl];
    }
    __syncthreads();
    #pragma unroll
    for (int i = 0; i < 16; i++){
        int q = threadIdx.x + (i << 8);
        int nl = q >> 6, d = q & 63;
        outL[((size_t)b*NN + n0 + nl)*DD + d] = S[d][nl];
    }
}

// ---------------- launch (R13 topology + partial precompute on s2) ----------------
extern "C" void kernel_launch(void* const* d_in, const int* in_sizes, int n_in,
                              void* d_out, int out_size) {
    const float* x   = (const float*)d_in[0];
    const float* h0  = (const float*)d_in[1];
    const float* adj = (const float*)d_in[2];
    const float* Wg  = (const float*)d_in[3];
    const float* bg  = (const float*)d_in[4];
    const float* Wc  = (const float*)d_in[5];
    const float* bc  = (const float*)d_in[6];
    float* out = (float*)d_out;

    void *pf, *pt;
    cudaGetSymbolAddress(&pf, g_fbuf);
    cudaGetSymbolAddress(&pt, g_tbuf);
    float* F = (float*)pf;
    float* T = (float*)pt;

    const int DSM = 6 * 32768;
    const int GSM = 3 * (128*144 + FS_B);
    const int CSM = 3 * (64*144  + FS_B);
    cudaFuncSetAttribute(diffuse_kernel<0>, cudaFuncAttributeMaxDynamicSharedMemorySize, DSM);
    cudaFuncSetAttribute(diffuse_kernel<1>, cudaFuncAttributeMaxDynamicSharedMemorySize, DSM);
    cudaFuncSetAttribute(gate_mma_kernel,   cudaFuncAttributeMaxDynamicSharedMemorySize, GSM);
    cudaFuncSetAttribute(cand_mma_kernel,   cudaFuncAttributeMaxDynamicSharedMemorySize, CSM);
    cudaFuncSetAttribute(gcx_kernel<128>,   cudaFuncAttributeMaxDynamicSharedMemorySize, GSM);
    cudaFuncSetAttribute(gcx_kernel<64>,    cudaFuncAttributeMaxDynamicSharedMemorySize, CSM);

    cudaStream_t s2;
    cudaStreamCreateWithFlags(&s2, cudaStreamNonBlocking);
    cudaEvent_t evFork, evP[TT];
    cudaEventCreateWithFlags(&evFork, cudaEventDisableTiming);
    for (int t = 0; t < TT; t++) cudaEventCreateWithFlags(&evP[t], cudaEventDisableTiming);

    // ---- main stream: shared prep (incl. W transposes, consumed by s2 partials) ----
    prep_adj_kernel<<<(int)(NN2/1024), 256>>>(adj);
    prep_adjT_kernel<<<dim3(NN/32, NN/32), 256>>>(adj);
    prep_T_kernel<0,1><<<dim3(NN/64, BB*TT), 256>>>(x,  T+T_X, nullptr);
    prep_W_kernel<<<(384*128+255)/256, 256>>>(Wg, T+T_WG, 128);
    prep_W_kernel<<<(384*64+255)/256, 256>>>(Wc, T+T_WC, 64);
    diffuse_kernel<1><<<dim3(16,16),256,DSM>>>(T+T_A, T+T_AT, T+T_S2, nullptr);  // S2'

    // ---- fork: x-diffusion + gate/cand x-partials per t ----
    cudaEventRecord(evFork, 0);
    cudaStreamWaitEvent(s2, evFork, 0);
    for (int t = 0; t < TT; t++){
        size_t xo = (size_t)t * MH * NN;
        diffuse_kernel<0><<<dim3(32,4),256,DSM,s2>>>(T+T_X+xo, T+T_A, T+T_XD1+xo, T+T_XD2+xo);
        gcx_kernel<128><<<dim3(16,8),256,GSM,s2>>>(t);
        gcx_kernel<64><<<dim3(16,8),256,CSM,s2>>>(t);
        cudaEventRecord(evP[t], s2);
    }

    // ---- main stream: recurrence prep + h-chain ----
    prep_T_kernel<1,0><<<dim3(NN/64, BB), 256>>>(h0, T+T_H, F+O_HF);

    for (int t = 0; t < TT; t++){
        diffuse_kernel<0><<<dim3(32,4),256,DSM>>>(T+T_H, T+T_A, T+T_HD1, T+T_HD2);
        cudaStreamWaitEvent(0, evP[t], 0);     // xd(t) + partials ready (joins fork at t=11)
        gate_mma_kernel<<<dim3(16,8),256,GSM>>>(bg, t);
        diffuse_kernel<0><<<dim3(32,4),256,DSM>>>(T+T_G, T+T_A, T+T_GD1, T+T_GD2);
        cand_mma_kernel<<<dim3(16,8),256,CSM>>>(bc, t);
    }

    final_out_kernel<<<dim3(NN/64, BB*TT), 256>>>(x, out);
    last_out_kernel<<<dim3(NN/64, BB), 256>>>(out + MXN);
}